// round 12
// baseline (speedup 1.0000x reference)
#include <cuda_runtime.h>
#include <cuda_bf16.h>
#include <mma.h>
#include <cstdint>

using namespace nvcuda;

#define BB 1024
#define CC 1000
#define HH 512
#define NEG_INF (__int_as_float(0xff800000))

#define GRID 272
#define BLK 256

// ---------------- scratch (__device__ globals; zero-initialized) ----------------
__device__ __nv_bfloat16 g_whi[1024 * 512];   // rows >= 1000 stay zero forever
__device__ __nv_bfloat16 g_wlo[1024 * 512];
__device__ float g_GA[1024 * 1024];           // split-K Gram partial (K 0..255)
__device__ float g_GB[1024 * 1024];           // split-K Gram partial (K 256..511)
__device__ float g_normA[1024];
__device__ float g_normB[1024];
__device__ float g_ymax[BB];
__device__ int   g_jmax[BB];
__device__ unsigned g_cnt;                    // barrier counter (self-resetting)

// ---------------- cp.async helpers ----------------
__device__ __forceinline__ uint32_t smem_u32(const void* p) {
    return (uint32_t)__cvta_generic_to_shared(p);
}
__device__ __forceinline__ void cp16(uint32_t dst, const void* src) {
    asm volatile("cp.async.cg.shared.global [%0], [%1], 16;" :: "r"(dst), "l"(src));
}
__device__ __forceinline__ void cp_commit() {
    asm volatile("cp.async.commit_group;" ::: "memory");
}
template <int N>
__device__ __forceinline__ void cp_wait() {
    asm volatile("cp.async.wait_group %0;" :: "n"(N) : "memory");
}

// ---------------- grid barrier: atomic arrive, VOLATILE-LOAD poll ----------------
// atomicInc wraps to 0 after 2*GRID increments (2 barriers x GRID CTAs) so the
// counter is clean for every graph replay. Polling uses plain volatile loads —
// L2 broadcasts the line; no atomic-unit serialization (R10's mistake).
__device__ __forceinline__ void gbar(int which) {
    __syncthreads();
    if (threadIdx.x == 0) {
        __threadfence();
        atomicInc(&g_cnt, 2u * GRID - 1u);
        volatile unsigned* c = &g_cnt;
        if (which == 1) {
            while (*c < (unsigned)GRID) __nanosleep(32);
        } else {
            while (*c != 0u) __nanosleep(32);
        }
        __threadfence();
    }
    __syncthreads();
}

// ---------------- gram tiling constants ----------------
#define NTT 16
#define NPAIR (NTT * (NTT + 1) / 2)   // 136 (x2 K-halves = 272 = GRID)
#define BKC 32
#define NKS2 8                        // chunks per K-half (256/32)
#define SST 40                        // bf16 smem stride: 80B rows, conflict-free
#define OPBYTES (64 * SST * 2)        // 5120 B per operand buffer

// ===========================================================================
__global__ void __launch_bounds__(BLK, 2)
k_all(const float* __restrict__ y,
      const float* __restrict__ w,
      const float* __restrict__ eps_p,
      const float* __restrict__ lip_p,
      float* __restrict__ out) {
    __shared__ __align__(16) char smem_raw[2 * 4 * OPBYTES];   // 40 KB
    __shared__ float sv[8];
    __shared__ int   si[8];

    const int bid = blockIdx.x;
    const int t = threadIdx.x;
    const int lane = t & 31, wid = t >> 5;

    // ================= Phase A: convert w + copy/argmax y (batched MLP) =====
    {
        const int i0 = bid * BLK + t;                 // < 69632
        const int i1 = i0 + GRID * BLK;
        const bool v0 = (i0 < CC * (HH / 4));
        const bool v1 = (i1 < CC * (HH / 4));
        float4 w0, w1;
        if (v0) w0 = __ldg((const float4*)w + i0);
        if (v1) w1 = __ldg((const float4*)w + i1);

        float4 vy[4];
        const bool yok = (t < CC / 4);
        #pragma unroll
        for (int r = 0; r < 4; r++) {
            const int b = bid + GRID * r;
            if (b < BB && yok)
                vy[r] = __ldg((const float4*)(y + (long)b * CC) + t);
        }

        // convert both w chunks
        #pragma unroll
        for (int c2 = 0; c2 < 2; c2++) {
            if (c2 ? !v1 : !v0) continue;
            const int idx = c2 ? i1 : i0;
            const float4 v = c2 ? w1 : w0;
            const int row = idx >> 7;
            const int q = idx & 127;
            const float e[4] = {v.x, v.y, v.z, v.w};
            uint64_t packhi = 0, packlo = 0;
            #pragma unroll
            for (int i = 0; i < 4; i++) {
                const __nv_bfloat16 h = __float2bfloat16(e[i]);
                const __nv_bfloat16 l = __float2bfloat16(e[i] - __bfloat162float(h));
                packhi |= (uint64_t)__bfloat16_as_ushort(h) << (16 * i);
                packlo |= (uint64_t)__bfloat16_as_ushort(l) << (16 * i);
            }
            *(uint64_t*)&g_whi[(long)row * HH + 4 * q] = packhi;
            *(uint64_t*)&g_wlo[(long)row * HH + 4 * q] = packlo;
        }

        // copy + argmax for up to 4 rows
        #pragma unroll
        for (int r = 0; r < 4; r++) {
            const int b = bid + GRID * r;
            if (b >= BB) break;
            float vmax = NEG_INF; int imax = 0x7fffffff;
            if (yok) {
                float* orow = out + (long)b * (CC + 1);
                const int c = t * 4;
                orow[c] = vy[r].x; orow[c + 1] = vy[r].y;
                orow[c + 2] = vy[r].z; orow[c + 3] = vy[r].w;
                vmax = vy[r].x; imax = c;
                if (vy[r].y > vmax) { vmax = vy[r].y; imax = c + 1; }
                if (vy[r].z > vmax) { vmax = vy[r].z; imax = c + 2; }
                if (vy[r].w > vmax) { vmax = vy[r].w; imax = c + 3; }
            }
            #pragma unroll
            for (int o = 16; o > 0; o >>= 1) {
                const float v2 = __shfl_xor_sync(0xffffffffu, vmax, o);
                const int   i2 = __shfl_xor_sync(0xffffffffu, imax, o);
                if (v2 > vmax || (v2 == vmax && i2 < imax)) { vmax = v2; imax = i2; }
            }
            if (lane == 0) { sv[wid] = vmax; si[wid] = imax; }
            __syncthreads();
            if (t == 0) {
                float bv = sv[0]; int bi = si[0];
                #pragma unroll
                for (int k = 1; k < 8; k++)
                    if (sv[k] > bv || (sv[k] == bv && si[k] < bi)) { bv = sv[k]; bi = si[k]; }
                g_ymax[b] = bv; g_jmax[b] = bi;
            }
            __syncthreads();
        }
    }

    gbar(1);

    // ================= Phase B: split-K bf16-split Gram (tensor pipe) =======
    {
        const int kh = bid & 1;
        int p = bid >> 1, ti = 0;
        while (p >= NTT - ti) { p -= NTT - ti; ti++; }
        const int tj = ti + p;
        const int k0 = kh * (HH / 2);

        const int wr = (wid >> 1) * 16;
        const int wc = (wid & 1) * 32;

        const int lrow = t >> 2;
        const int seg = t & 3;
        const long aoff = (long)(ti * 64 + lrow) * HH + k0 + seg * 8;
        const long boff = (long)(tj * 64 + lrow) * HH + k0 + seg * 8;
        const uint32_t sdst = smem_u32(smem_raw) + lrow * (SST * 2) + seg * 16;
        const __nv_bfloat16* gsrc[4] = {g_whi, g_wlo, g_whi, g_wlo};

        auto issue = [&](int chunk, int buf) {
            const long co = (long)chunk * BKC;
            #pragma unroll
            for (int op = 0; op < 4; op++) {
                const __nv_bfloat16* src = gsrc[op] + ((op < 2) ? aoff : boff) + co;
                cp16(sdst + (buf * 4 + op) * OPBYTES, src);
            }
        };

        wmma::fragment<wmma::accumulator, 16, 16, 16, float> acc[2];
        wmma::fill_fragment(acc[0], 0.f);
        wmma::fill_fragment(acc[1], 0.f);

        issue(0, 0); cp_commit();
        issue(1, 1); cp_commit();

        #pragma unroll 1
        for (int ks = 0; ks < NKS2; ks++) {
            const int buf = ks & 1;
            cp_wait<1>();
            __syncthreads();

            const __nv_bfloat16* sAhi = (const __nv_bfloat16*)(smem_raw + (buf * 4 + 0) * OPBYTES);
            const __nv_bfloat16* sAlo = (const __nv_bfloat16*)(smem_raw + (buf * 4 + 1) * OPBYTES);
            const __nv_bfloat16* sBhi = (const __nv_bfloat16*)(smem_raw + (buf * 4 + 2) * OPBYTES);
            const __nv_bfloat16* sBlo = (const __nv_bfloat16*)(smem_raw + (buf * 4 + 3) * OPBYTES);

            #pragma unroll
            for (int kk = 0; kk < BKC; kk += 16) {
                wmma::fragment<wmma::matrix_a, 16, 16, 16, __nv_bfloat16, wmma::row_major> ah, al;
                wmma::fragment<wmma::matrix_b, 16, 16, 16, __nv_bfloat16, wmma::col_major> bh[2], bl[2];
                wmma::load_matrix_sync(ah, sAhi + wr * SST + kk, SST);
                wmma::load_matrix_sync(al, sAlo + wr * SST + kk, SST);
                #pragma unroll
                for (int j = 0; j < 2; j++) {
                    wmma::load_matrix_sync(bh[j], sBhi + (wc + 16 * j) * SST + kk, SST);
                    wmma::load_matrix_sync(bl[j], sBlo + (wc + 16 * j) * SST + kk, SST);
                }
                #pragma unroll
                for (int j = 0; j < 2; j++) {
                    wmma::mma_sync(acc[j], ah, bh[j], acc[j]);
                    wmma::mma_sync(acc[j], ah, bl[j], acc[j]);
                    wmma::mma_sync(acc[j], al, bh[j], acc[j]);
                }
            }
            __syncthreads();
            if (ks + 2 < NKS2) issue(ks + 2, buf);
            cp_commit();
        }

        cp_wait<0>();
        __syncthreads();                   // reuse smem as float Cs[64][68]
        float* Cs = (float*)smem_raw;
        #pragma unroll
        for (int j = 0; j < 2; j++)
            wmma::store_matrix_sync(Cs + wr * 68 + wc + 16 * j, acc[j], 68,
                                    wmma::mem_row_major);
        __syncthreads();

        float* G = kh ? g_GB : g_GA;
        for (int idx = t; idx < 64 * 16; idx += BLK) {       // upper tile
            const int r = idx >> 4, c4 = idx & 15;
            const float4 v = *(const float4*)(Cs + r * 68 + c4 * 4);
            *(float4*)&G[(long)(ti * 64 + r) * 1024 + tj * 64 + c4 * 4] = v;
        }
        for (int idx = t; idx < 64 * 16; idx += BLK) {       // mirror
            const int c = idx >> 4, r4 = idx & 15;
            float4 v;
            v.x = Cs[(4 * r4 + 0) * 68 + c];
            v.y = Cs[(4 * r4 + 1) * 68 + c];
            v.z = Cs[(4 * r4 + 2) * 68 + c];
            v.w = Cs[(4 * r4 + 3) * 68 + c];
            *(float4*)&G[(long)(tj * 64 + c) * 1024 + ti * 64 + 4 * r4] = v;
        }
        if (ti == tj && t < 64)
            (kh ? g_normB : g_normA)[ti * 64 + t] = Cs[t * 68 + t];
    }

    gbar(2);

    // ================= Phase C: y_bot (4 rows/CTA) ==========================
    const float s  = (*eps_p) * fabsf(*lip_p);
    const float s2 = s * s;
    #pragma unroll 1
    for (int r = 0; r < 4; r++) {
        const int b = bid + GRID * r;
        if (b >= BB) break;
        const int   j    = g_jmax[b];
        const float ymax = g_ymax[b];
        const float nj   = g_normA[j] + g_normB[j];

        float best = NEG_INF;
        if (t < CC / 4) {
            const float4 vy = __ldg((const float4*)(y + (long)b * CC) + t);
            const float4 ga = *((const float4*)(g_GA + (long)j * 1024) + t);
            const float4 gb = *((const float4*)(g_GB + (long)j * 1024) + t);
            const float4 na = *((const float4*)g_normA + t);
            const float4 nb = *((const float4*)g_normB + t);
            const float ye[4] = {vy.x, vy.y, vy.z, vy.w};
            const float ge[4] = {ga.x + gb.x, ga.y + gb.y, ga.z + gb.z, ga.w + gb.w};
            const float ne[4] = {na.x + nb.x, na.y + nb.y, na.z + nb.z, na.w + nb.w};
            #pragma unroll
            for (int e = 0; e < 4; e++) {
                if (ye[e] == ymax) continue;    // ref masks y==ymax -> -inf
                float sq = fmaf(-2.f, ge[e], nj + ne[e]);
                if (sq < 0.f) sq = 0.f;
                const float d = best - ye[e];
                if (d <= 0.f || sq * s2 > d * d)
                    best = fmaxf(best, fmaf(s, sqrtf(sq), ye[e]));
            }
        }
        #pragma unroll
        for (int o = 16; o > 0; o >>= 1)
            best = fmaxf(best, __shfl_xor_sync(0xffffffffu, best, o));
        if (lane == 0) sv[wid] = best;
        __syncthreads();
        if (t == 0) {
            float rr = sv[0];
            #pragma unroll
            for (int k = 1; k < 8; k++) rr = fmaxf(rr, sv[k]);
            out[(long)b * (CC + 1) + CC] = rr;
        }
        __syncthreads();
    }
}

// ---------------------------------------------------------------------------
extern "C" void kernel_launch(void* const* d_in, const int* in_sizes, int n_in,
                              void* d_out, int out_size) {
    const float* y   = (const float*)d_in[0];
    const float* w   = (const float*)d_in[1];
    const float* eps = (const float*)d_in[2];
    const float* lip = (const float*)d_in[3];
    float* out = (float*)d_out;

    k_all<<<GRID, BLK>>>(y, w, eps, lip, out);
}

// round 13
// speedup vs baseline: 1.4583x; 1.4583x over previous
#include <cuda_runtime.h>
#include <cuda_fp16.h>
#include <mma.h>
#include <cstdint>

using namespace nvcuda;

#define BB 1024
#define CC 1000
#define HH 512
#define NEG_INF (__int_as_float(0xff800000))

// ---------------- scratch (__device__ globals; zero-initialized) ----------------
__device__ __half g_wh[1024 * 512];           // fp16(w); rows >= 1000 stay zero
__device__ float g_GA[1024 * 1024];           // split-K Gram partial (K 0..255)
__device__ float g_GB[1024 * 1024];           // split-K Gram partial (K 256..511)
__device__ float g_normA[1024];               // diagonal partials (consistent norms)
__device__ float g_normB[1024];
__device__ float g_ymax[BB];
__device__ int   g_jmax[BB];

// ---------------- cp.async helpers ----------------
__device__ __forceinline__ uint32_t smem_u32(const void* p) {
    return (uint32_t)__cvta_generic_to_shared(p);
}
__device__ __forceinline__ void cp16(uint32_t dst, const void* src) {
    asm volatile("cp.async.cg.shared.global [%0], [%1], 16;" :: "r"(dst), "l"(src));
}
__device__ __forceinline__ void cp_commit() {
    asm volatile("cp.async.commit_group;" ::: "memory");
}
template <int N>
__device__ __forceinline__ void cp_wait() {
    asm volatile("cp.async.wait_group %0;" :: "n"(N) : "memory");
}

// ---------------------------------------------------------------------------
// k_pre: bid < 256  -> w f32 -> fp16 convert (2 float4 per thread, 1 cvt/2 elems)
//        bid >= 256 -> one y-row: copy into out + argmax/max
// ---------------------------------------------------------------------------
#define NCONV 256

__global__ void __launch_bounds__(256)
k_pre(const float* __restrict__ w,
      const float* __restrict__ y,
      float* __restrict__ out) {
    const int t = threadIdx.x;

    if (blockIdx.x < NCONV) {
        const int i0 = (blockIdx.x * 256 + t) * 2;     // float4 index, +0/+1
        // 128000 float4s total; i0 < 131072 -> guard
        #pragma unroll
        for (int u = 0; u < 2; u++) {
            const int idx = i0 + u;
            if (idx < CC * (HH / 4)) {
                const float4 v = __ldg((const float4*)w + idx);
                uint32_t p0, p1;
                asm("cvt.rn.f16x2.f32 %0, %1, %2;" : "=r"(p0) : "f"(v.y), "f"(v.x));
                asm("cvt.rn.f16x2.f32 %0, %1, %2;" : "=r"(p1) : "f"(v.w), "f"(v.z));
                *(uint2*)&g_wh[idx * 4] = make_uint2(p0, p1);
            }
        }
        return;
    }

    // ---------------- copy + argmax: one y-row per block ----------------
    __shared__ float sv[8];
    __shared__ int   si[8];
    const int b = blockIdx.x - NCONV;
    const int lane = t & 31, wid = t >> 5;
    float* orow = out + (long)b * (CC + 1);

    float vmax = NEG_INF; int imax = 0x7fffffff;
    if (t < CC / 4) {
        const float4 vy = __ldg((const float4*)(y + (long)b * CC) + t);
        const int c = t * 4;
        orow[c] = vy.x; orow[c + 1] = vy.y; orow[c + 2] = vy.z; orow[c + 3] = vy.w;
        vmax = vy.x; imax = c;
        if (vy.y > vmax) { vmax = vy.y; imax = c + 1; }
        if (vy.z > vmax) { vmax = vy.z; imax = c + 2; }
        if (vy.w > vmax) { vmax = vy.w; imax = c + 3; }
    }
    #pragma unroll
    for (int o = 16; o > 0; o >>= 1) {
        const float v2 = __shfl_xor_sync(0xffffffffu, vmax, o);
        const int   i2 = __shfl_xor_sync(0xffffffffu, imax, o);
        if (v2 > vmax || (v2 == vmax && i2 < imax)) { vmax = v2; imax = i2; }
    }
    if (lane == 0) { sv[wid] = vmax; si[wid] = imax; }
    __syncthreads();
    if (t == 0) {
        float bv = sv[0]; int bi = si[0];
        #pragma unroll
        for (int k = 1; k < 8; k++)
            if (sv[k] > bv || (sv[k] == bv && si[k] < bi)) { bv = sv[k]; bi = si[k]; }
        g_ymax[b] = bv; g_jmax[b] = bi;
    }
}

// ---------------------------------------------------------------------------
// k_gram: SINGLE-PASS fp16 Gram on tensor pipe. 272 CTAs (136 upper-tri 64x64
// tile-pairs x 2 K-halves), 256 thr, warp tile 16x32. BKC=64 (4 chunks/half).
// cp.async double-buffered. Diagonal tiles emit consistent norms.
// ---------------------------------------------------------------------------
#define NTT 16
#define NPAIR (NTT * (NTT + 1) / 2)   // 136
#define NGRAM (2 * NPAIR)             // 272
#define BKC 64
#define NKS2 4                        // chunks per K-half (256/64)
#define SST 72                        // fp16 stride: 144B rows; ldsm banks 36r%32 distinct
#define OPBYTES (64 * SST * 2)        // 9216 B per operand buffer

__global__ void __launch_bounds__(256, 2)
k_gram() {
    __shared__ __align__(16) char smem_raw[2 * 2 * OPBYTES];   // 36,864 B
    float* Cs = (float*)smem_raw;                              // epilogue 64x68 f32

    const int t = threadIdx.x;
    const int wid = t >> 5;
    const int wr = (wid >> 1) * 16;   // 0..48
    const int wc = (wid & 1) * 32;    // 0,32

    const int kh = blockIdx.x & 1;
    int p = blockIdx.x >> 1, ti = 0;
    while (p >= NTT - ti) { p -= NTT - ti; ti++; }
    const int tj = ti + p;
    const int k0 = kh * (HH / 2);

    // loader: row = t>>2 (0..63), seg = t&3 -> 32B (2x cp16) per operand
    const int lrow = t >> 2;
    const int seg = t & 3;
    const long aoff = (long)(ti * 64 + lrow) * HH + k0 + seg * 16;
    const long boff = (long)(tj * 64 + lrow) * HH + k0 + seg * 16;
    const uint32_t sdst = smem_u32(smem_raw) + lrow * (SST * 2) + seg * 32;

    auto issue = [&](int chunk, int buf) {
        const long co = (long)chunk * BKC;
        const __half* sa = g_wh + aoff + co;
        const __half* sb = g_wh + boff + co;
        const uint32_t da = sdst + (buf * 2 + 0) * OPBYTES;
        const uint32_t db = sdst + (buf * 2 + 1) * OPBYTES;
        cp16(da, sa); cp16(da + 16, sa + 8);
        cp16(db, sb); cp16(db + 16, sb + 8);
    };

    wmma::fragment<wmma::accumulator, 16, 16, 16, float> acc[2];
    wmma::fill_fragment(acc[0], 0.f);
    wmma::fill_fragment(acc[1], 0.f);

    issue(0, 0); cp_commit();
    issue(1, 1); cp_commit();

    #pragma unroll 1
    for (int ks = 0; ks < NKS2; ks++) {
        const int buf = ks & 1;
        cp_wait<1>();
        __syncthreads();

        const __half* sA = (const __half*)(smem_raw + (buf * 2 + 0) * OPBYTES);
        const __half* sB = (const __half*)(smem_raw + (buf * 2 + 1) * OPBYTES);

        #pragma unroll
        for (int kk = 0; kk < BKC; kk += 16) {
            wmma::fragment<wmma::matrix_a, 16, 16, 16, __half, wmma::row_major> af;
            wmma::fragment<wmma::matrix_b, 16, 16, 16, __half, wmma::col_major> bf[2];
            wmma::load_matrix_sync(af, sA + wr * SST + kk, SST);
            wmma::load_matrix_sync(bf[0], sB + wc * SST + kk, SST);
            wmma::load_matrix_sync(bf[1], sB + (wc + 16) * SST + kk, SST);
            wmma::mma_sync(acc[0], af, bf[0], acc[0]);
            wmma::mma_sync(acc[1], af, bf[1], acc[1]);
        }
        __syncthreads();
        if (ks + 2 < NKS2) issue(ks + 2, buf);
        cp_commit();
    }

    cp_wait<0>();
    __syncthreads();                   // reuse smem as float Cs[64][68]
    #pragma unroll
    for (int j = 0; j < 2; j++)
        wmma::store_matrix_sync(Cs + wr * 68 + wc + 16 * j, acc[j], 68,
                                wmma::mem_row_major);
    __syncthreads();

    float* G = kh ? g_GB : g_GA;
    for (int idx = t; idx < 64 * 16; idx += 256) {       // upper tile
        const int r = idx >> 4, c4 = idx & 15;
        const float4 v = *(const float4*)(Cs + r * 68 + c4 * 4);
        *(float4*)&G[(long)(ti * 64 + r) * 1024 + tj * 64 + c4 * 4] = v;
    }
    for (int idx = t; idx < 64 * 16; idx += 256) {       // mirror (transposed)
        const int c = idx >> 4, r4 = idx & 15;
        float4 v;
        v.x = Cs[(4 * r4 + 0) * 68 + c];
        v.y = Cs[(4 * r4 + 1) * 68 + c];
        v.z = Cs[(4 * r4 + 2) * 68 + c];
        v.w = Cs[(4 * r4 + 3) * 68 + c];
        *(float4*)&G[(long)(tj * 64 + c) * 1024 + ti * 64 + 4 * r4] = v;
    }
    if (ti == tj && t < 64)            // consistent norms from diagonal
        (kh ? g_normB : g_normA)[ti * 64 + t] = Cs[t * 68 + t];
}

// ---------------------------------------------------------------------------
// k_bot: y_bot. 1024 blocks x 256 threads; batched loads, pruned sqrt.
// ---------------------------------------------------------------------------
__global__ void __launch_bounds__(256)
k_bot(const float* __restrict__ y,
      const float* __restrict__ eps_p,
      const float* __restrict__ lip_p,
      float* __restrict__ out) {
    const int b = blockIdx.x;
    const int t = threadIdx.x;
    const int lane = t & 31, wid = t >> 5;
    __shared__ float sm[8];

    const float s  = (*eps_p) * fabsf(*lip_p);
    const float s2 = s * s;
    const int   j    = g_jmax[b];
    const float ymax = g_ymax[b];
    const float nj   = g_normA[j] + g_normB[j];

    float best = NEG_INF;
    if (t < CC / 4) {
        const float4 vy = __ldg((const float4*)(y + (long)b * CC) + t);
        const float4 ga = *((const float4*)(g_GA + (long)j * 1024) + t);
        const float4 gb = *((const float4*)(g_GB + (long)j * 1024) + t);
        const float4 na = *((const float4*)g_normA + t);
        const float4 nb = *((const float4*)g_normB + t);
        const float ye[4] = {vy.x, vy.y, vy.z, vy.w};
        const float ge[4] = {ga.x + gb.x, ga.y + gb.y, ga.z + gb.z, ga.w + gb.w};
        const float ne[4] = {na.x + nb.x, na.y + nb.y, na.z + nb.z, na.w + nb.w};
        #pragma unroll
        for (int e = 0; e < 4; e++) {
            if (ye[e] == ymax) continue;        // ref masks y==ymax -> -inf
            float sq = fmaf(-2.f, ge[e], nj + ne[e]);
            if (sq < 0.f) sq = 0.f;
            const float d = best - ye[e];
            if (d <= 0.f || sq * s2 > d * d)
                best = fmaxf(best, fmaf(s, sqrtf(sq), ye[e]));
        }
    }
    #pragma unroll
    for (int o = 16; o > 0; o >>= 1)
        best = fmaxf(best, __shfl_xor_sync(0xffffffffu, best, o));
    if (lane == 0) sm[wid] = best;
    __syncthreads();
    if (t == 0) {
        float r = sm[0];
        #pragma unroll
        for (int k = 1; k < 8; k++) r = fmaxf(r, sm[k]);
        out[(long)b * (CC + 1) + CC] = r;
    }
}

// ---------------------------------------------------------------------------
extern "C" void kernel_launch(void* const* d_in, const int* in_sizes, int n_in,
                              void* d_out, int out_size) {
    const float* y   = (const float*)d_in[0];
    const float* w   = (const float*)d_in[1];
    const float* eps = (const float*)d_in[2];
    const float* lip = (const float*)d_in[3];
    float* out = (float*)d_out;

    k_pre<<<NCONV + BB, 256>>>(w, y, out);
    k_gram<<<NGRAM, 256>>>();
    k_bot<<<BB, 256>>>(y, eps, lip, out);
}

// round 14
// speedup vs baseline: 1.6000x; 1.0972x over previous
#include <cuda_runtime.h>
#include <cuda_fp16.h>
#include <mma.h>
#include <cstdint>

using namespace nvcuda;

#define BB 1024
#define CC 1000
#define HH 512
#define NEG_INF (__int_as_float(0xff800000))

// ---------------- scratch (__device__ globals; zero-initialized) ----------------
__device__ __half g_wh[1024 * 512];           // fp16(w); rows >= 1000 stay zero
__device__ float g_GA[1024 * 1024];           // split-K Gram partial (K 0..255)
__device__ float g_GB[1024 * 1024];           // split-K Gram partial (K 256..511)
__device__ float g_normA[1024];               // diagonal partials (consistent norms)
__device__ float g_normB[1024];

// ---------------- cp.async helpers ----------------
__device__ __forceinline__ uint32_t smem_u32(const void* p) {
    return (uint32_t)__cvta_generic_to_shared(p);
}
__device__ __forceinline__ void cp16(uint32_t dst, const void* src) {
    asm volatile("cp.async.cg.shared.global [%0], [%1], 16;" :: "r"(dst), "l"(src));
}
__device__ __forceinline__ void cp_commit() {
    asm volatile("cp.async.commit_group;" ::: "memory");
}
template <int N>
__device__ __forceinline__ void cp_wait() {
    asm volatile("cp.async.wait_group %0;" :: "n"(N) : "memory");
}

// ---------------------------------------------------------------------------
// k_conv: w f32 -> fp16. 512 blocks x 256 threads, one float4 per thread.
// ---------------------------------------------------------------------------
__global__ void __launch_bounds__(256)
k_conv(const float* __restrict__ w) {
    const int idx = blockIdx.x * 256 + threadIdx.x;   // float4 index
    if (idx < CC * (HH / 4)) {
        const float4 v = __ldg((const float4*)w + idx);
        uint32_t p0, p1;
        asm("cvt.rn.f16x2.f32 %0, %1, %2;" : "=r"(p0) : "f"(v.y), "f"(v.x));
        asm("cvt.rn.f16x2.f32 %0, %1, %2;" : "=r"(p1) : "f"(v.w), "f"(v.z));
        *(uint2*)&g_wh[idx * 4] = make_uint2(p0, p1);
    }
}

// ---------------------------------------------------------------------------
// k_gram: single-pass fp16 Gram on tensor pipe. 272 CTAs (136 upper-tri 64x64
// tile-pairs x 2 K-halves), 256 thr, warp tile 16x32, BKC=64, cp.async
// double-buffered. Diagonal tiles emit consistent norms.
// ---------------------------------------------------------------------------
#define NTT 16
#define NPAIR (NTT * (NTT + 1) / 2)   // 136
#define NGRAM (2 * NPAIR)             // 272
#define BKC 64
#define NKS2 4                        // chunks per K-half (256/64)
#define SST 72                        // fp16 stride: 144B rows; conflict-free ldsm
#define OPBYTES (64 * SST * 2)        // 9216 B per operand buffer

__global__ void __launch_bounds__(256, 2)
k_gram() {
    __shared__ __align__(16) char smem_raw[2 * 2 * OPBYTES];   // 36,864 B
    float* Cs = (float*)smem_raw;                              // epilogue 64x68 f32

    const int t = threadIdx.x;
    const int wid = t >> 5;
    const int wr = (wid >> 1) * 16;   // 0..48
    const int wc = (wid & 1) * 32;    // 0,32

    const int kh = blockIdx.x & 1;
    int p = blockIdx.x >> 1, ti = 0;
    while (p >= NTT - ti) { p -= NTT - ti; ti++; }
    const int tj = ti + p;
    const int k0 = kh * (HH / 2);

    const int lrow = t >> 2;
    const int seg = t & 3;
    const long aoff = (long)(ti * 64 + lrow) * HH + k0 + seg * 16;
    const long boff = (long)(tj * 64 + lrow) * HH + k0 + seg * 16;
    const uint32_t sdst = smem_u32(smem_raw) + lrow * (SST * 2) + seg * 32;

    auto issue = [&](int chunk, int buf) {
        const long co = (long)chunk * BKC;
        const __half* sa = g_wh + aoff + co;
        const __half* sb = g_wh + boff + co;
        const uint32_t da = sdst + (buf * 2 + 0) * OPBYTES;
        const uint32_t db = sdst + (buf * 2 + 1) * OPBYTES;
        cp16(da, sa); cp16(da + 16, sa + 8);
        cp16(db, sb); cp16(db + 16, sb + 8);
    };

    wmma::fragment<wmma::accumulator, 16, 16, 16, float> acc[2];
    wmma::fill_fragment(acc[0], 0.f);
    wmma::fill_fragment(acc[1], 0.f);

    issue(0, 0); cp_commit();
    issue(1, 1); cp_commit();

    #pragma unroll 1
    for (int ks = 0; ks < NKS2; ks++) {
        const int buf = ks & 1;
        cp_wait<1>();
        __syncthreads();

        const __half* sA = (const __half*)(smem_raw + (buf * 2 + 0) * OPBYTES);
        const __half* sB = (const __half*)(smem_raw + (buf * 2 + 1) * OPBYTES);

        #pragma unroll
        for (int kk = 0; kk < BKC; kk += 16) {
            wmma::fragment<wmma::matrix_a, 16, 16, 16, __half, wmma::row_major> af;
            wmma::fragment<wmma::matrix_b, 16, 16, 16, __half, wmma::col_major> bf[2];
            wmma::load_matrix_sync(af, sA + wr * SST + kk, SST);
            wmma::load_matrix_sync(bf[0], sB + wc * SST + kk, SST);
            wmma::load_matrix_sync(bf[1], sB + (wc + 16) * SST + kk, SST);
            wmma::mma_sync(acc[0], af, bf[0], acc[0]);
            wmma::mma_sync(acc[1], af, bf[1], acc[1]);
        }
        __syncthreads();
        if (ks + 2 < NKS2) issue(ks + 2, buf);
        cp_commit();
    }

    cp_wait<0>();
    __syncthreads();                   // reuse smem as float Cs[64][68]
    #pragma unroll
    for (int j = 0; j < 2; j++)
        wmma::store_matrix_sync(Cs + wr * 68 + wc + 16 * j, acc[j], 68,
                                wmma::mem_row_major);
    __syncthreads();

    float* G = kh ? g_GB : g_GA;
    for (int idx = t; idx < 64 * 16; idx += 256) {       // upper tile
        const int r = idx >> 4, c4 = idx & 15;
        const float4 v = *(const float4*)(Cs + r * 68 + c4 * 4);
        *(float4*)&G[(long)(ti * 64 + r) * 1024 + tj * 64 + c4 * 4] = v;
    }
    for (int idx = t; idx < 64 * 16; idx += 256) {       // mirror (transposed)
        const int c = idx >> 4, r4 = idx & 15;
        float4 v;
        v.x = Cs[(4 * r4 + 0) * 68 + c];
        v.y = Cs[(4 * r4 + 1) * 68 + c];
        v.z = Cs[(4 * r4 + 2) * 68 + c];
        v.w = Cs[(4 * r4 + 3) * 68 + c];
        *(float4*)&G[(long)(tj * 64 + c) * 1024 + ti * 64 + 4 * r4] = v;
    }
    if (ti == tj && t < 64)            // consistent norms from diagonal
        (kh ? g_normB : g_normA)[ti * 64 + t] = Cs[t * 68 + t];
}

// ---------------------------------------------------------------------------
// k_bot: fused per-row copy + argmax + y_bot. 1024 blocks x 256 threads.
// Reads y exactly once.
// ---------------------------------------------------------------------------
__global__ void __launch_bounds__(256)
k_bot(const float* __restrict__ y,
      const float* __restrict__ eps_p,
      const float* __restrict__ lip_p,
      float* __restrict__ out) {
    const int b = blockIdx.x;
    const int t = threadIdx.x;
    const int lane = t & 31, wid = t >> 5;
    __shared__ float sv[8];
    __shared__ int   si[8];
    __shared__ float s_ymax;
    __shared__ int   s_j;

    float* orow = out + (long)b * (CC + 1);

    // ---- load y once, copy, block argmax (first-index tie-break) ----
    float4 vy = make_float4(NEG_INF, NEG_INF, NEG_INF, NEG_INF);
    const bool yok = (t < CC / 4);
    float vmax = NEG_INF; int imax = 0x7fffffff;
    if (yok) {
        vy = __ldg((const float4*)(y + (long)b * CC) + t);
        const int c = t * 4;
        orow[c] = vy.x; orow[c + 1] = vy.y; orow[c + 2] = vy.z; orow[c + 3] = vy.w;
        vmax = vy.x; imax = c;
        if (vy.y > vmax) { vmax = vy.y; imax = c + 1; }
        if (vy.z > vmax) { vmax = vy.z; imax = c + 2; }
        if (vy.w > vmax) { vmax = vy.w; imax = c + 3; }
    }
    #pragma unroll
    for (int o = 16; o > 0; o >>= 1) {
        const float v2 = __shfl_xor_sync(0xffffffffu, vmax, o);
        const int   i2 = __shfl_xor_sync(0xffffffffu, imax, o);
        if (v2 > vmax || (v2 == vmax && i2 < imax)) { vmax = v2; imax = i2; }
    }
    if (lane == 0) { sv[wid] = vmax; si[wid] = imax; }
    __syncthreads();
    if (t == 0) {
        float bv = sv[0]; int bi = si[0];
        #pragma unroll
        for (int k = 1; k < 8; k++)
            if (sv[k] > bv || (sv[k] == bv && si[k] < bi)) { bv = sv[k]; bi = si[k]; }
        s_ymax = bv; s_j = bi;
    }
    __syncthreads();
    const float ymax = s_ymax;
    const int j = s_j;

    // ---- y_bot with pruned sqrt ----
    const float s  = (*eps_p) * fabsf(*lip_p);
    const float s2 = s * s;
    const float nj = g_normA[j] + g_normB[j];

    float best = NEG_INF;
    if (yok) {
        const float4 ga = *((const float4*)(g_GA + (long)j * 1024) + t);
        const float4 gb = *((const float4*)(g_GB + (long)j * 1024) + t);
        const float4 na = *((const float4*)g_normA + t);
        const float4 nb = *((const float4*)g_normB + t);
        const float ye[4] = {vy.x, vy.y, vy.z, vy.w};
        const float ge[4] = {ga.x + gb.x, ga.y + gb.y, ga.z + gb.z, ga.w + gb.w};
        const float ne[4] = {na.x + nb.x, na.y + nb.y, na.z + nb.z, na.w + nb.w};
        #pragma unroll
        for (int e = 0; e < 4; e++) {
            if (ye[e] == ymax) continue;        // ref masks y==ymax -> -inf
            float sq = fmaf(-2.f, ge[e], nj + ne[e]);
            if (sq < 0.f) sq = 0.f;
            const float d = best - ye[e];
            if (d <= 0.f || sq * s2 > d * d)
                best = fmaxf(best, fmaf(s, sqrtf(sq), ye[e]));
        }
    }
    #pragma unroll
    for (int o = 16; o > 0; o >>= 1)
        best = fmaxf(best, __shfl_xor_sync(0xffffffffu, best, o));
    if (lane == 0) sv[wid] = best;
    __syncthreads();
    if (t == 0) {
        float r = sv[0];
        #pragma unroll
        for (int k = 1; k < 8; k++) r = fmaxf(r, sv[k]);
        orow[CC] = r;
    }
}

// ---------------------------------------------------------------------------
extern "C" void kernel_launch(void* const* d_in, const int* in_sizes, int n_in,
                              void* d_out, int out_size) {
    const float* y   = (const float*)d_in[0];
    const float* w   = (const float*)d_in[1];
    const float* eps = (const float*)d_in[2];
    const float* lip = (const float*)d_in[3];
    float* out = (float*)d_out;

    k_conv<<<512, 256>>>(w);
    k_gram<<<NGRAM, 256>>>();
    k_bot<<<BB, 256>>>(y, eps, lip, out);
}

// round 15
// speedup vs baseline: 1.8488x; 1.1555x over previous
#include <cuda_runtime.h>
#include <cuda_fp16.h>
#include <mma.h>
#include <cstdint>

using namespace nvcuda;

#define BB 1024
#define CC 1000
#define HH 512
#define NEG_INF (__int_as_float(0xff800000))

// ---------------- scratch (__device__ globals; zero-initialized) ----------------
__device__ float g_GA[1024 * 1024];           // split-K Gram partial (K 0..255)
__device__ float g_GB[1024 * 1024];           // split-K Gram partial (K 256..511)
__device__ float g_normA[1024];               // diagonal partials (consistent norms)
__device__ float g_normB[1024];

// ---------------------------------------------------------------------------
// k_gram: fused convert+Gram. 272 CTAs (136 upper-tri 64x64 tile-pairs x 2
// K-halves), 256 thr. Each CTA loads its own f32 tiles from w (L2-resident),
// converts to fp16 into smem ONCE (full K-half), then runs the entire MMA
// sweep with no further syncs. No precompute kernel, no g_wh.
// ---------------------------------------------------------------------------
#define NTT 16
#define NPAIR (NTT * (NTT + 1) / 2)   // 136
#define NGRAM (2 * NPAIR)             // 272
#define KHALF (HH / 2)                // 256
#define SST2 264                      // fp16 smem stride (528B rows): 33r%32
                                      // distinct -> conflict-free ldsm phases
#define OPHALF (64 * SST2)            // fp16 elems per operand buffer
#define SMEMSZ (2 * OPHALF * 2)       // 67584 B dynamic smem

extern __shared__ char dsm[];

__global__ void __launch_bounds__(256, 2)
k_gram(const float* __restrict__ w) {
    __half* sA = (__half*)dsm;
    __half* sB = sA + OPHALF;
    float* Cs = (float*)dsm;          // epilogue overlay: 64x68 f32

    const int t = threadIdx.x;
    const int wid = t >> 5;
    const int wr = (wid >> 1) * 16;   // 0..48
    const int wc = (wid & 1) * 32;    // 0,32

    const int kh = blockIdx.x & 1;
    int p = blockIdx.x >> 1, ti = 0;
    while (p >= NTT - ti) { p -= NTT - ti; ti++; }
    const int tj = ti + p;
    const int k0 = kh * KHALF;

    // -------- Phase 1: load f32 tiles, convert, store fp16 to smem --------
    // Per operand: 64 rows x 256 cols = 4096 float4s; 16 per thread.
    #pragma unroll
    for (int i = 0; i < 16; i++) {
        const int idx = i * 256 + t;          // < 4096
        const int fr = idx >> 6;              // row in tile 0..63
        const int fc = (idx & 63) * 4;        // f32 col 0..252
        const int ra = min(ti * 64 + fr, CC - 1);   // clamp: no OOB w reads
        const int rb = min(tj * 64 + fr, CC - 1);
        const float4 va = __ldg((const float4*)(w + (long)ra * HH + k0 + fc));
        const float4 vb = __ldg((const float4*)(w + (long)rb * HH + k0 + fc));
        uint32_t a0, a1, b0, b1;
        asm("cvt.rn.f16x2.f32 %0, %1, %2;" : "=r"(a0) : "f"(va.y), "f"(va.x));
        asm("cvt.rn.f16x2.f32 %0, %1, %2;" : "=r"(a1) : "f"(va.w), "f"(va.z));
        asm("cvt.rn.f16x2.f32 %0, %1, %2;" : "=r"(b0) : "f"(vb.y), "f"(vb.x));
        asm("cvt.rn.f16x2.f32 %0, %1, %2;" : "=r"(b1) : "f"(vb.w), "f"(vb.z));
        *(uint2*)&sA[fr * SST2 + fc] = make_uint2(a0, a1);
        *(uint2*)&sB[fr * SST2 + fc] = make_uint2(b0, b1);
    }
    __syncthreads();

    // -------- Phase 2: MMA sweep, K=256 in 16 steps, no syncs --------
    wmma::fragment<wmma::accumulator, 16, 16, 16, float> acc[2];
    wmma::fill_fragment(acc[0], 0.f);
    wmma::fill_fragment(acc[1], 0.f);

    #pragma unroll
    for (int kk = 0; kk < KHALF; kk += 16) {
        wmma::fragment<wmma::matrix_a, 16, 16, 16, __half, wmma::row_major> af;
        wmma::fragment<wmma::matrix_b, 16, 16, 16, __half, wmma::col_major> bf[2];
        wmma::load_matrix_sync(af, sA + wr * SST2 + kk, SST2);
        wmma::load_matrix_sync(bf[0], sB + wc * SST2 + kk, SST2);
        wmma::load_matrix_sync(bf[1], sB + (wc + 16) * SST2 + kk, SST2);
        wmma::mma_sync(acc[0], af, bf[0], acc[0]);
        wmma::mma_sync(acc[1], af, bf[1], acc[1]);
    }

    // -------- Epilogue: smem round-trip, coalesced upper + mirror --------
    __syncthreads();                  // done reading sA/sB; overlay Cs
    #pragma unroll
    for (int j = 0; j < 2; j++)
        wmma::store_matrix_sync(Cs + wr * 68 + wc + 16 * j, acc[j], 68,
                                wmma::mem_row_major);
    __syncthreads();

    float* G = kh ? g_GB : g_GA;
    for (int idx = t; idx < 64 * 16; idx += 256) {       // upper tile
        const int r = idx >> 4, c4 = idx & 15;
        const float4 v = *(const float4*)(Cs + r * 68 + c4 * 4);
        *(float4*)&G[(long)(ti * 64 + r) * 1024 + tj * 64 + c4 * 4] = v;
    }
    for (int idx = t; idx < 64 * 16; idx += 256) {       // mirror (transposed)
        const int c = idx >> 4, r4 = idx & 15;
        float4 v;
        v.x = Cs[(4 * r4 + 0) * 68 + c];
        v.y = Cs[(4 * r4 + 1) * 68 + c];
        v.z = Cs[(4 * r4 + 2) * 68 + c];
        v.w = Cs[(4 * r4 + 3) * 68 + c];
        *(float4*)&G[(long)(tj * 64 + c) * 1024 + ti * 64 + 4 * r4] = v;
    }
    if (ti == tj && t < 64)            // consistent norms from diagonal
        (kh ? g_normB : g_normA)[ti * 64 + t] = Cs[t * 68 + t];
}

// ---------------------------------------------------------------------------
// k_bot: fused per-row copy + argmax + y_bot. 1024 blocks x 256 threads.
// ---------------------------------------------------------------------------
__global__ void __launch_bounds__(256)
k_bot(const float* __restrict__ y,
      const float* __restrict__ eps_p,
      const float* __restrict__ lip_p,
      float* __restrict__ out) {
    const int b = blockIdx.x;
    const int t = threadIdx.x;
    const int lane = t & 31, wid = t >> 5;
    __shared__ float sv[8];
    __shared__ int   si[8];
    __shared__ float s_ymax;
    __shared__ int   s_j;

    float* orow = out + (long)b * (CC + 1);

    // ---- load y once, copy, block argmax (first-index tie-break) ----
    float4 vy = make_float4(NEG_INF, NEG_INF, NEG_INF, NEG_INF);
    const bool yok = (t < CC / 4);
    float vmax = NEG_INF; int imax = 0x7fffffff;
    if (yok) {
        vy = __ldg((const float4*)(y + (long)b * CC) + t);
        const int c = t * 4;
        orow[c] = vy.x; orow[c + 1] = vy.y; orow[c + 2] = vy.z; orow[c + 3] = vy.w;
        vmax = vy.x; imax = c;
        if (vy.y > vmax) { vmax = vy.y; imax = c + 1; }
        if (vy.z > vmax) { vmax = vy.z; imax = c + 2; }
        if (vy.w > vmax) { vmax = vy.w; imax = c + 3; }
    }
    #pragma unroll
    for (int o = 16; o > 0; o >>= 1) {
        const float v2 = __shfl_xor_sync(0xffffffffu, vmax, o);
        const int   i2 = __shfl_xor_sync(0xffffffffu, imax, o);
        if (v2 > vmax || (v2 == vmax && i2 < imax)) { vmax = v2; imax = i2; }
    }
    if (lane == 0) { sv[wid] = vmax; si[wid] = imax; }
    __syncthreads();
    if (t == 0) {
        float bv = sv[0]; int bi = si[0];
        #pragma unroll
        for (int k = 1; k < 8; k++)
            if (sv[k] > bv || (sv[k] == bv && si[k] < bi)) { bv = sv[k]; bi = si[k]; }
        s_ymax = bv; s_j = bi;
    }
    __syncthreads();
    const float ymax = s_ymax;
    const int j = s_j;

    // ---- y_bot with pruned sqrt ----
    const float s  = (*eps_p) * fabsf(*lip_p);
    const float s2 = s * s;
    const float nj = g_normA[j] + g_normB[j];

    float best = NEG_INF;
    if (yok) {
        const float4 ga = *((const float4*)(g_GA + (long)j * 1024) + t);
        const float4 gb = *((const float4*)(g_GB + (long)j * 1024) + t);
        const float4 na = *((const float4*)g_normA + t);
        const float4 nb = *((const float4*)g_normB + t);
        const float ye[4] = {vy.x, vy.y, vy.z, vy.w};
        const float ge[4] = {ga.x + gb.x, ga.y + gb.y, ga.z + gb.z, ga.w + gb.w};
        const float ne[4] = {na.x + nb.x, na.y + nb.y, na.z + nb.z, na.w + nb.w};
        #pragma unroll
        for (int e = 0; e < 4; e++) {
            if (ye[e] == ymax) continue;        // ref masks y==ymax -> -inf
            float sq = fmaf(-2.f, ge[e], nj + ne[e]);
            if (sq < 0.f) sq = 0.f;
            const float d = best - ye[e];
            if (d <= 0.f || sq * s2 > d * d)
                best = fmaxf(best, fmaf(s, sqrtf(sq), ye[e]));
        }
    }
    #pragma unroll
    for (int o = 16; o > 0; o >>= 1)
        best = fmaxf(best, __shfl_xor_sync(0xffffffffu, best, o));
    if (lane == 0) sv[wid] = best;
    __syncthreads();
    if (t == 0) {
        float r = sv[0];
        #pragma unroll
        for (int k = 1; k < 8; k++) r = fmaxf(r, sv[k]);
        orow[CC] = r;
    }
}

// ---------------------------------------------------------------------------
extern "C" void kernel_launch(void* const* d_in, const int* in_sizes, int n_in,
                              void* d_out, int out_size) {
    const float* y   = (const float*)d_in[0];
    const float* w   = (const float*)d_in[1];
    const float* eps = (const float*)d_in[2];
    const float* lip = (const float*)d_in[3];
    float* out = (float*)d_out;

    static bool attr = false;
    if (!attr) {
        cudaFuncSetAttribute(k_gram, cudaFuncAttributeMaxDynamicSharedMemorySize,
                             SMEMSZ);
        attr = true;
    }

    k_gram<<<NGRAM, 256, SMEMSZ>>>(w);
    k_bot<<<BB, 256>>>(y, eps, lip, out);
}